// round 10
// baseline (speedup 1.0000x reference)
#include <cuda_runtime.h>
#include <cstdint>

#define IN_CHAN 4096
#define BATCH   16
#define NTOT    (3 * IN_CHAN)          // 12288 stacked W rows (q,k,v)
#define KSPLIT  16
#define KS_LEN  (IN_CHAN / KSPLIT)     // 256 k per block
#define ROWS_PB 128                    // W rows per block (4 warps x 32)
#define NNODES  32
#define NCHUNK  16
#define CHLEN   (IN_CHAN / NCHUNK)     // 256
#define QHALF   4.0f
#define LOG2E   1.4426950408889634f
#define PI_F    3.14159265358979323846f

#define XW      132                    // x smem row pitch in b32 words (264 bf16)

// Scratch (device globals; no allocation allowed anywhere)
__device__ float g_part[KSPLIT * NTOT * BATCH];       // split-K partials
__device__ float g_nodes[BATCH][NCHUNK][2][NNODES];   // per j-chunk partial F,G

__device__ __forceinline__ float ex2(float x) {
    float r;
    asm("ex2.approx.ftz.f32 %0, %1;" : "=f"(r) : "f"(x));
    return r;
}
// pack two fp32 into bf16x2 (consistent convention for A and B fragments)
__device__ __forceinline__ uint32_t packbf(float hi_elem, float lo_elem) {
    uint32_t r;
    asm("cvt.rn.bf16x2.f32 %0, %1, %2;" : "=r"(r) : "f"(hi_elem), "f"(lo_elem));
    return r;
}
// split a float2 (k, k+1 adjacent) into bf16x2 hi and lo parts
__device__ __forceinline__ void split2(float2 f, uint32_t& hi, uint32_t& lo) {
    hi = packbf(f.y, f.x);
    float f0h = __uint_as_float(hi << 16);
    float f1h = __uint_as_float(hi & 0xffff0000u);
    lo = packbf(f.y - f1h, f.x - f0h);
}
// m16n8k16 bf16 MMA, fp32 accumulate
__device__ __forceinline__ void mma16816(float* d, const uint32_t* a,
                                         uint32_t b0, uint32_t b1) {
    asm volatile(
        "mma.sync.aligned.m16n8k16.row.col.f32.bf16.bf16.f32 "
        "{%0,%1,%2,%3}, {%4,%5,%6,%7}, {%8,%9}, {%0,%1,%2,%3};"
        : "+f"(d[0]), "+f"(d[1]), "+f"(d[2]), "+f"(d[3])
        : "r"(a[0]), "r"(a[1]), "r"(a[2]), "r"(a[3]), "r"(b0), "r"(b1));
}

// ---------------------------------------------------------------------------
// Kernel 1: QKV GEMM on tensor cores (bf16x3 split), split-K.
// Block 128 thr = 4 warps x 32 rows x 16 batches x 256 k.  W never in smem:
// A fragments LDG.64 direct from global (sector-perfect), converted to
// bf16 hi/lo in regs.  x converted once to padded smem bf16 (hi & lo),
// B-fragment LDS.32 conflict-free (pitch 132 words -> bank=(4n+c+k/2)%32).
// Per k16 per warp: 8 LDG.64 + ~48 cvt + 8 LDS + 12 MMA.  DRAM-bound.
// ---------------------------------------------------------------------------
__global__ __launch_bounds__(128) void qkv_gemm_kernel(
    const float* __restrict__ x,
    const float* __restrict__ wq,
    const float* __restrict__ wk,
    const float* __restrict__ wv)
{
    __shared__ uint32_t xhi[BATCH * XW];   // [n][k/2] bf16 pairs, padded
    __shared__ uint32_t xlo[BATCH * XW];

    const int tid  = threadIdx.x;
    const int wid  = tid >> 5;
    const int lane = tid & 31;

    const int gn0 = blockIdx.x * ROWS_PB;
    const int mat = gn0 >> 12;
    const int n0  = gn0 & (IN_CHAN - 1);
    const int kb  = blockIdx.y * KS_LEN;
    const float* w = (mat == 0) ? wq : (mat == 1) ? wk : wv;

    // ---- stage x slice as bf16 hi/lo:  16 b x 128 float2 per row ----
#pragma unroll
    for (int i = 0; i < 16; ++i) {
        int idx = tid + i * 128;        // [0,2048)
        int b   = idx >> 7;
        int kw  = idx & 127;            // float2 index within row
        float2 f = *(const float2*)(x + (size_t)b * IN_CHAN + kb + kw * 2);
        uint32_t h, l;
        split2(f, h, l);
        xhi[b * XW + kw] = h;
        xlo[b * XW + kw] = l;
    }
    __syncthreads();

    // warp owns rows m0..m0+31 (2 m-tiles of 16)
    const int m0   = n0 + wid * 32;
    const int la4  = lane >> 2;         // 0..7
    const int c0   = (lane & 3) * 2;    // col pair base within k16
    // per-m-tile row pointers (rows la4, la4+8 within tile)
    const float* p00 = w + (size_t)(m0 + la4)      * IN_CHAN + kb + c0;
    const float* p01 = w + (size_t)(m0 + la4 + 8)  * IN_CHAN + kb + c0;
    const float* p10 = w + (size_t)(m0 + 16 + la4) * IN_CHAN + kb + c0;
    const float* p11 = w + (size_t)(m0 + 24 + la4) * IN_CHAN + kb + c0;

    float d[2][2][4];                   // [m-tile][n-tile][4]
#pragma unroll
    for (int t = 0; t < 2; ++t)
#pragma unroll
        for (int n = 0; n < 2; ++n)
#pragma unroll
            for (int j = 0; j < 4; ++j) d[t][n][j] = 0.f;

    const int brow0 = (lane >> 2) * XW;        // n = lane/4 (n-tile 0)
    const int brow1 = (8 + (lane >> 2)) * XW;  // n-tile 1

#pragma unroll 2
    for (int k = 0; k < KS_LEN; k += 16) {
        // A fragment loads (fp32), 8 LDG.64
        float2 f00 = *(const float2*)(p00 + k);
        float2 f01 = *(const float2*)(p01 + k);
        float2 f02 = *(const float2*)(p00 + k + 8);
        float2 f03 = *(const float2*)(p01 + k + 8);
        float2 f10 = *(const float2*)(p10 + k);
        float2 f11 = *(const float2*)(p11 + k);
        float2 f12 = *(const float2*)(p10 + k + 8);
        float2 f13 = *(const float2*)(p11 + k + 8);

        uint32_t ah[2][4], al[2][4];
        split2(f00, ah[0][0], al[0][0]);
        split2(f01, ah[0][1], al[0][1]);
        split2(f02, ah[0][2], al[0][2]);
        split2(f03, ah[0][3], al[0][3]);
        split2(f10, ah[1][0], al[1][0]);
        split2(f11, ah[1][1], al[1][1]);
        split2(f12, ah[1][2], al[1][2]);
        split2(f13, ah[1][3], al[1][3]);

        // B fragments: word index k/2 + (lane&3), +4 for k+8 half
        const int kw = (k >> 1) + (lane & 3);
        uint32_t b0h0 = xhi[brow0 + kw],     b1h0 = xhi[brow0 + kw + 4];
        uint32_t b0l0 = xlo[brow0 + kw],     b1l0 = xlo[brow0 + kw + 4];
        uint32_t b0h1 = xhi[brow1 + kw],     b1h1 = xhi[brow1 + kw + 4];
        uint32_t b0l1 = xlo[brow1 + kw],     b1l1 = xlo[brow1 + kw + 4];

#pragma unroll
        for (int t = 0; t < 2; ++t) {
            mma16816(d[t][0], ah[t], b0h0, b1h0);   // hi*hi
            mma16816(d[t][0], ah[t], b0l0, b1l0);   // hi*lo
            mma16816(d[t][0], al[t], b0h0, b1h0);   // lo*hi
            mma16816(d[t][1], ah[t], b0h1, b1h1);
            mma16816(d[t][1], ah[t], b0l1, b1l1);
            mma16816(d[t][1], al[t], b0h1, b1h1);
        }
    }

    // epilogue: d{0,1}: row la4, batches c0,c0+1; d{2,3}: row la4+8
    const int p = blockIdx.y;
#pragma unroll
    for (int t = 0; t < 2; ++t) {
#pragma unroll
        for (int n = 0; n < 2; ++n) {
            int gnA = gn0 + wid * 32 + t * 16 + la4;
            int bcol = n * 8 + c0;
            float* dstA = g_part + ((size_t)p * NTOT + gnA) * BATCH + bcol;
            *(float2*)dstA = make_float2(d[t][n][0], d[t][n][1]);
            float* dstB = g_part + ((size_t)p * NTOT + gnA + 8) * BATCH + bcol;
            *(float2*)dstB = make_float2(d[t][n][2], d[t][n][3]);
        }
    }
}

// ---------------------------------------------------------------------------
// Kernel 2: nodes. Reduces its own k,v chunk from g_part inline (+bias),
// then evaluates F,G partials at 32 fixed Chebyshev nodes (domain +-QHALF).
// grid (16 batches, 16 chunks) x 512 thr.
// ---------------------------------------------------------------------------
__global__ __launch_bounds__(512) void attn_nodes_kernel(
    const float* __restrict__ bk,
    const float* __restrict__ bv)
{
    __shared__ float ks[CHLEN], vs[CHLEN];
    const int b   = blockIdx.x;
    const int ch  = blockIdx.y;
    const int tid = threadIdx.x;

    {
        int n   = tid & (CHLEN - 1);
        int sel = tid >> 8;             // 0 = k (mat 1), 1 = v (mat 2)
        int gn  = (1 + sel) * IN_CHAN + ch * CHLEN + n;
        float s = 0.f;
#pragma unroll
        for (int p = 0; p < KSPLIT; ++p)
            s += g_part[((size_t)p * NTOT + gn) * BATCH + b];
        s += (sel ? bv : bk)[ch * CHLEN + n];
        if (sel) vs[n] = s;
        else     ks[n] = s;
    }
    __syncthreads();

    const int node = tid >> 4;
    const int sub  = tid & 15;

    const float xt = QHALF * cosf(PI_F * (node + 0.5f) / NNODES);
    const float a  = xt * LOG2E;

    float aF = 0.f, aG = 0.f;
#pragma unroll
    for (int j = sub; j < CHLEN; j += 16) {
        float e = ex2(a * ks[j]);
        aG += e;
        aF = fmaf(e, vs[j], aF);
    }
#pragma unroll
    for (int o = 8; o; o >>= 1) {
        aF += __shfl_xor_sync(0xffffffffu, aF, o);
        aG += __shfl_xor_sync(0xffffffffu, aG, o);
    }
    if (sub == 0) {
        g_nodes[b][ch][0][node] = aF;
        g_nodes[b][ch][1][node] = aG;
    }
}

// ---------------------------------------------------------------------------
// Kernel 3: fused fit + eval. Sum node chunks, 32x32 DCT -> Chebyshev
// coeffs, inline split-K reduce of q (+bq), Clenshaw -> out.
// grid (32 x-chunks, 16 batches) x 128 thr.
// ---------------------------------------------------------------------------
__global__ __launch_bounds__(128) void attn_eval_kernel(
    const float* __restrict__ bq,
    float* __restrict__ out)
{
    __shared__ float Fv[NNODES], Gv[NNODES], tab[128], cF[NNODES], cG[NNODES];
    const int b   = blockIdx.y;
    const int tid = threadIdx.x;

    if (tid < 64) {
        int node = tid & 31;
        int sel  = tid >> 5;
        float v = 0.f;
#pragma unroll
        for (int ch = 0; ch < NCHUNK; ++ch)
            v += g_nodes[b][ch][sel][node];
        if (sel == 0) Fv[node] = v;
        else          Gv[node] = v;
    }
    tab[tid] = cosf((PI_F / 64.0f) * (float)tid);
    __syncthreads();

    if (tid < 64) {
        int m = tid & 31;
        const float* src = (tid < 32) ? Fv : Gv;
        float c = 0.f;
#pragma unroll
        for (int t = 0; t < NNODES; ++t)
            c = fmaf(src[t], tab[(m * (2 * t + 1)) & 127], c);
        c *= 2.0f / NNODES;
        if (tid < 32) cF[m] = c;
        else          cG[m] = c;
    }

    const int i = blockIdx.x * 128 + tid;
    float q = 0.f;
#pragma unroll
    for (int p = 0; p < KSPLIT; ++p)
        q += g_part[((size_t)p * NTOT + i) * BATCH + b];
    q += bq[i];

    __syncthreads();

    float y = q * (1.0f / QHALF);
    y = fminf(1.f, fmaxf(-1.f, y));
    const float y2 = 2.f * y;

    float f1 = 0.f, f2 = 0.f, g1 = 0.f, g2 = 0.f;
#pragma unroll
    for (int m = NNODES - 1; m >= 1; --m) {
        float tf = fmaf(y2, f1, cF[m] - f2);
        f2 = f1; f1 = tf;
        float tg = fmaf(y2, g1, cG[m] - g2);
        g2 = g1; g1 = tg;
    }
    float F = fmaf(y, f1, 0.5f * cF[0]) - f2;
    float G = fmaf(y, g1, 0.5f * cG[0]) - g2;

    out[(size_t)b * IN_CHAN + i] = F / G;
}

// ---------------------------------------------------------------------------
extern "C" void kernel_launch(void* const* d_in, const int* in_sizes, int n_in,
                              void* d_out, int out_size)
{
    (void)in_sizes; (void)n_in; (void)out_size;
    const float* x  = (const float*)d_in[0];
    const float* wq = (const float*)d_in[1];
    const float* bq = (const float*)d_in[2];
    const float* wk = (const float*)d_in[3];
    const float* bk = (const float*)d_in[4];
    const float* wv = (const float*)d_in[5];
    const float* bv = (const float*)d_in[6];
    float* out = (float*)d_out;

    qkv_gemm_kernel<<<dim3(NTOT / ROWS_PB, KSPLIT), 128>>>(x, wq, wk, wv);
    attn_nodes_kernel<<<dim3(BATCH, NCHUNK), 512>>>(bk, bv);
    attn_eval_kernel<<<dim3(IN_CHAN / 128, BATCH), 128>>>(bq, out);
}

// round 11
// speedup vs baseline: 1.2044x; 1.2044x over previous
#include <cuda_runtime.h>
#include <cstdint>

#define IN_CHAN 4096
#define BATCH   16
#define NTOT    (3 * IN_CHAN)          // 12288 stacked W rows (q,k,v)
#define KSPLIT  16
#define KS_LEN  (IN_CHAN / KSPLIT)     // 256 k per block
#define ROWS_PB 128                    // W rows per block (4 warps x 32)
#define NNODES  32
#define NCHUNK  16
#define CHLEN   (IN_CHAN / NCHUNK)     // 256
#define QHALF   4.0f
#define LOG2E   1.4426950408889634f
#define PI_F    3.14159265358979323846f

#define XW      132                    // x smem row pitch in b32 words (264 bf16)

// Scratch (device globals; no allocation allowed anywhere)
__device__ float g_part[KSPLIT * NTOT * BATCH];       // split-K partials
__device__ float g_nodes[BATCH][NCHUNK][2][NNODES];   // per j-chunk partial F,G

__device__ __forceinline__ float ex2(float x) {
    float r;
    asm("ex2.approx.ftz.f32 %0, %1;" : "=f"(r) : "f"(x));
    return r;
}
// pack two fp32 into bf16x2 (consistent convention for A and B fragments)
__device__ __forceinline__ uint32_t packbf(float hi_elem, float lo_elem) {
    uint32_t r;
    asm("cvt.rn.bf16x2.f32 %0, %1, %2;" : "=r"(r) : "f"(hi_elem), "f"(lo_elem));
    return r;
}
// split a float2 (k, k+1 adjacent) into bf16x2 hi and lo parts
__device__ __forceinline__ void split2(float2 f, uint32_t& hi, uint32_t& lo) {
    hi = packbf(f.y, f.x);
    float f0h = __uint_as_float(hi << 16);
    float f1h = __uint_as_float(hi & 0xffff0000u);
    lo = packbf(f.y - f1h, f.x - f0h);
}
// m16n8k16 bf16 MMA, fp32 accumulate
__device__ __forceinline__ void mma16816(float* d, const uint32_t* a,
                                         uint32_t b0, uint32_t b1) {
    asm volatile(
        "mma.sync.aligned.m16n8k16.row.col.f32.bf16.bf16.f32 "
        "{%0,%1,%2,%3}, {%4,%5,%6,%7}, {%8,%9}, {%0,%1,%2,%3};"
        : "+f"(d[0]), "+f"(d[1]), "+f"(d[2]), "+f"(d[3])
        : "r"(a[0]), "r"(a[1]), "r"(a[2]), "r"(a[3]), "r"(b0), "r"(b1));
}

// ---------------------------------------------------------------------------
// Kernel 1: QKV GEMM on tensor cores (bf16x3 split), split-K, prefetched.
// Block 128 thr = 4 warps x 32 rows x 16 batches x 256 k.  W never in smem:
// A fragments LDG.64 direct from global (sector-perfect), PREFETCHED one
// k16 step ahead so DRAM latency overlaps the cvt/LDS/MMA work of the
// current step.  x converted once to padded smem bf16 (hi & lo);
// B-fragment LDS.32 conflict-free (pitch 132 words).
// ---------------------------------------------------------------------------
__global__ __launch_bounds__(128) void qkv_gemm_kernel(
    const float* __restrict__ x,
    const float* __restrict__ wq,
    const float* __restrict__ wk,
    const float* __restrict__ wv)
{
    __shared__ uint32_t xhi[BATCH * XW];   // [n][k/2] bf16 pairs, padded
    __shared__ uint32_t xlo[BATCH * XW];

    const int tid  = threadIdx.x;
    const int wid  = tid >> 5;
    const int lane = tid & 31;

    const int gn0 = blockIdx.x * ROWS_PB;
    const int mat = gn0 >> 12;
    const int n0  = gn0 & (IN_CHAN - 1);
    const int kb  = blockIdx.y * KS_LEN;
    const float* w = (mat == 0) ? wq : (mat == 1) ? wk : wv;

    // ---- stage x slice as bf16 hi/lo:  16 b x 128 float2 per row ----
#pragma unroll
    for (int i = 0; i < 16; ++i) {
        int idx = tid + i * 128;        // [0,2048)
        int b   = idx >> 7;
        int kw  = idx & 127;            // float2 index within row
        float2 f = *(const float2*)(x + (size_t)b * IN_CHAN + kb + kw * 2);
        uint32_t h, l;
        split2(f, h, l);
        xhi[b * XW + kw] = h;
        xlo[b * XW + kw] = l;
    }
    __syncthreads();

    // warp owns rows m0..m0+31 (2 m-tiles of 16)
    const int m0   = n0 + wid * 32;
    const int la4  = lane >> 2;         // 0..7
    const int c0   = (lane & 3) * 2;    // col pair base within k16
    const float* p00 = w + (size_t)(m0 + la4)      * IN_CHAN + kb + c0;
    const float* p01 = w + (size_t)(m0 + la4 + 8)  * IN_CHAN + kb + c0;
    const float* p10 = w + (size_t)(m0 + 16 + la4) * IN_CHAN + kb + c0;
    const float* p11 = w + (size_t)(m0 + 24 + la4) * IN_CHAN + kb + c0;

    float d[2][2][4];                   // [m-tile][n-tile][4]
#pragma unroll
    for (int t = 0; t < 2; ++t)
#pragma unroll
        for (int n = 0; n < 2; ++n)
#pragma unroll
            for (int j = 0; j < 4; ++j) d[t][n][j] = 0.f;

    const int brow0 = (lane >> 2) * XW;        // n-tile 0 row base
    const int brow1 = (8 + (lane >> 2)) * XW;  // n-tile 1

    // software prefetch registers (depth 1, 8 float2)
    float2 pf[8];
#define PF_LOAD(kk)                                   \
    do {                                              \
        pf[0] = *(const float2*)(p00 + (kk));         \
        pf[1] = *(const float2*)(p01 + (kk));         \
        pf[2] = *(const float2*)(p00 + (kk) + 8);     \
        pf[3] = *(const float2*)(p01 + (kk) + 8);     \
        pf[4] = *(const float2*)(p10 + (kk));         \
        pf[5] = *(const float2*)(p11 + (kk));         \
        pf[6] = *(const float2*)(p10 + (kk) + 8);     \
        pf[7] = *(const float2*)(p11 + (kk) + 8);     \
    } while (0)

    PF_LOAD(0);

#pragma unroll 4
    for (int k = 0; k < KS_LEN; k += 16) {
        float2 cur[8];
#pragma unroll
        for (int i = 0; i < 8; ++i) cur[i] = pf[i];
        if (k + 16 < KS_LEN) PF_LOAD(k + 16);

        uint32_t ah[2][4], al[2][4];
        split2(cur[0], ah[0][0], al[0][0]);
        split2(cur[1], ah[0][1], al[0][1]);
        split2(cur[2], ah[0][2], al[0][2]);
        split2(cur[3], ah[0][3], al[0][3]);
        split2(cur[4], ah[1][0], al[1][0]);
        split2(cur[5], ah[1][1], al[1][1]);
        split2(cur[6], ah[1][2], al[1][2]);
        split2(cur[7], ah[1][3], al[1][3]);

        // B fragments: word index k/2 + (lane&3), +4 for the k+8 half
        const int kw = (k >> 1) + (lane & 3);
        uint32_t b0h0 = xhi[brow0 + kw],     b1h0 = xhi[brow0 + kw + 4];
        uint32_t b0l0 = xlo[brow0 + kw],     b1l0 = xlo[brow0 + kw + 4];
        uint32_t b0h1 = xhi[brow1 + kw],     b1h1 = xhi[brow1 + kw + 4];
        uint32_t b0l1 = xlo[brow1 + kw],     b1l1 = xlo[brow1 + kw + 4];

#pragma unroll
        for (int t = 0; t < 2; ++t) {
            mma16816(d[t][0], ah[t], b0h0, b1h0);   // hi*hi
            mma16816(d[t][0], ah[t], b0l0, b1l0);   // hi*lo
            mma16816(d[t][0], al[t], b0h0, b1h0);   // lo*hi
            mma16816(d[t][1], ah[t], b0h1, b1h1);
            mma16816(d[t][1], ah[t], b0l1, b1l1);
            mma16816(d[t][1], al[t], b0h1, b1h1);
        }
    }
#undef PF_LOAD

    // epilogue: d[..][0,1]: row la4, batches c0,c0+1; d[..][2,3]: row la4+8
    const int p = blockIdx.y;
#pragma unroll
    for (int t = 0; t < 2; ++t) {
#pragma unroll
        for (int n = 0; n < 2; ++n) {
            int gnA = gn0 + wid * 32 + t * 16 + la4;
            int bcol = n * 8 + c0;
            float* dstA = g_part + ((size_t)p * NTOT + gnA) * BATCH + bcol;
            *(float2*)dstA = make_float2(d[t][n][0], d[t][n][1]);
            float* dstB = g_part + ((size_t)p * NTOT + gnA + 8) * BATCH + bcol;
            *(float2*)dstB = make_float2(d[t][n][2], d[t][n][3]);
        }
    }
}

// ---------------------------------------------------------------------------
// Kernel 2: nodes. Reduces its own k,v chunk from g_part inline (+bias),
// then evaluates F,G partials at 32 fixed Chebyshev nodes (domain +-QHALF).
// grid (16 batches, 16 chunks) x 512 thr.
// ---------------------------------------------------------------------------
__global__ __launch_bounds__(512) void attn_nodes_kernel(
    const float* __restrict__ bk,
    const float* __restrict__ bv)
{
    __shared__ float ks[CHLEN], vs[CHLEN];
    const int b   = blockIdx.x;
    const int ch  = blockIdx.y;
    const int tid = threadIdx.x;

    {
        int n   = tid & (CHLEN - 1);
        int sel = tid >> 8;             // 0 = k (mat 1), 1 = v (mat 2)
        int gn  = (1 + sel) * IN_CHAN + ch * CHLEN + n;
        float s = 0.f;
#pragma unroll
        for (int p = 0; p < KSPLIT; ++p)
            s += g_part[((size_t)p * NTOT + gn) * BATCH + b];
        s += (sel ? bv : bk)[ch * CHLEN + n];
        if (sel) vs[n] = s;
        else     ks[n] = s;
    }
    __syncthreads();

    const int node = tid >> 4;
    const int sub  = tid & 15;

    const float xt = QHALF * cosf(PI_F * (node + 0.5f) / NNODES);
    const float a  = xt * LOG2E;

    float aF = 0.f, aG = 0.f;
#pragma unroll
    for (int j = sub; j < CHLEN; j += 16) {
        float e = ex2(a * ks[j]);
        aG += e;
        aF = fmaf(e, vs[j], aF);
    }
#pragma unroll
    for (int o = 8; o; o >>= 1) {
        aF += __shfl_xor_sync(0xffffffffu, aF, o);
        aG += __shfl_xor_sync(0xffffffffu, aG, o);
    }
    if (sub == 0) {
        g_nodes[b][ch][0][node] = aF;
        g_nodes[b][ch][1][node] = aG;
    }
}

// ---------------------------------------------------------------------------
// Kernel 3: fused fit + eval. Sum node chunks, 32x32 DCT -> Chebyshev
// coeffs, inline split-K reduce of q (+bq), Clenshaw -> out.
// grid (32 x-chunks, 16 batches) x 128 thr.
// ---------------------------------------------------------------------------
__global__ __launch_bounds__(128) void attn_eval_kernel(
    const float* __restrict__ bq,
    float* __restrict__ out)
{
    __shared__ float Fv[NNODES], Gv[NNODES], tab[128], cF[NNODES], cG[NNODES];
    const int b   = blockIdx.y;
    const int tid = threadIdx.x;

    if (tid < 64) {
        int node = tid & 31;
        int sel  = tid >> 5;
        float v = 0.f;
#pragma unroll
        for (int ch = 0; ch < NCHUNK; ++ch)
            v += g_nodes[b][ch][sel][node];
        if (sel == 0) Fv[node] = v;
        else          Gv[node] = v;
    }
    tab[tid] = cosf((PI_F / 64.0f) * (float)tid);
    __syncthreads();

    if (tid < 64) {
        int m = tid & 31;
        const float* src = (tid < 32) ? Fv : Gv;
        float c = 0.f;
#pragma unroll
        for (int t = 0; t < NNODES; ++t)
            c = fmaf(src[t], tab[(m * (2 * t + 1)) & 127], c);
        c *= 2.0f / NNODES;
        if (tid < 32) cF[m] = c;
        else          cG[m] = c;
    }

    const int i = blockIdx.x * 128 + tid;
    float q = 0.f;
#pragma unroll
    for (int p = 0; p < KSPLIT; ++p)
        q += g_part[((size_t)p * NTOT + i) * BATCH + b];
    q += bq[i];

    __syncthreads();

    float y = q * (1.0f / QHALF);
    y = fminf(1.f, fmaxf(-1.f, y));
    const float y2 = 2.f * y;

    float f1 = 0.f, f2 = 0.f, g1 = 0.f, g2 = 0.f;
#pragma unroll
    for (int m = NNODES - 1; m >= 1; --m) {
        float tf = fmaf(y2, f1, cF[m] - f2);
        f2 = f1; f1 = tf;
        float tg = fmaf(y2, g1, cG[m] - g2);
        g2 = g1; g1 = tg;
    }
    float F = fmaf(y, f1, 0.5f * cF[0]) - f2;
    float G = fmaf(y, g1, 0.5f * cG[0]) - g2;

    out[(size_t)b * IN_CHAN + i] = F / G;
}

// ---------------------------------------------------------------------------
extern "C" void kernel_launch(void* const* d_in, const int* in_sizes, int n_in,
                              void* d_out, int out_size)
{
    (void)in_sizes; (void)n_in; (void)out_size;
    const float* x  = (const float*)d_in[0];
    const float* wq = (const float*)d_in[1];
    const float* bq = (const float*)d_in[2];
    const float* wk = (const float*)d_in[3];
    const float* bk = (const float*)d_in[4];
    const float* wv = (const float*)d_in[5];
    const float* bv = (const float*)d_in[6];
    float* out = (float*)d_out;

    qkv_gemm_kernel<<<dim3(NTOT / ROWS_PB, KSPLIT), 128>>>(x, wq, wk, wv);
    attn_nodes_kernel<<<dim3(BATCH, NCHUNK), 512>>>(bk, bv);
    attn_eval_kernel<<<dim3(IN_CHAN / 128, BATCH), 128>>>(bq, out);
}